// round 7
// baseline (speedup 1.0000x reference)
#include <cuda_runtime.h>
#include <cuda_bf16.h>
#include <mma.h>
#include <cstdint>

using namespace nvcuda;

#define N_IMG 16
#define H_IMG 112
#define W_IMG 112
#define C_IN  256
#define C_OUT 256

// ============================ conv kernel ============================
// Implicit GEMM: M = N*H*W = 200704 pixels, N = 256 couts, K = 9*256 = 2304.
// CTA: 64 pixels x 256 couts, 256 threads = 8 warps in 2(M) x 4(N) grid,
// warp tile 32x64 = 2x4 wmma 16x16x16 bf16 accumulators.
// K loop: 36 chunks (9 taps x 4 channel-quarters of 64).
// A tile 64x64 bf16 and B tile 256x64 bf16 staged in smem (pitch 72 elems =
// 144B, multiple of 16B as wmma requires). int32 inputs converted to bf16
// inline (values in [-128,127]: exact). Boundary taps zero-filled explicitly.
// OUTPUT IS WRITTEN AS FLOAT32 VALUES (integer-exact in fp32): the harness
// compares d_out as float32 — storing int32 bit patterns produces NaNs.
static constexpr int APITCH = 72;
static constexpr int BPITCH = 72;
static constexpr int B_OFF  = 64 * APITCH;               // 4608 elems
static constexpr int SMEM_ELEMS = B_OFF + 256 * BPITCH;  // 23040 elems = 46080 B

__global__ void __launch_bounds__(256)
conv_kernel(const int* __restrict__ x, const int* __restrict__ w,
            float* __restrict__ out) {
    __shared__ __align__(128) __nv_bfloat16 sm[SMEM_ELEMS];

    const int tid = threadIdx.x;
    const int wid = tid >> 5;
    const int wm  = wid >> 2;          // 0..1
    const int wn  = wid & 3;           // 0..3
    const int m_base = blockIdx.x * 64;

    // per-thread staging geometry: rows r0 and r0+32 (A) / +32*it (B),
    // 8-element column group c8
    const int r0 = tid >> 3;           // 0..31
    const int c8 = (tid & 7) * 8;      // 0,8,...,56

    int hh[2], ww[2], nn[2];
    #pragma unroll
    for (int j = 0; j < 2; j++) {
        const int pix = m_base + r0 + j * 32;
        nn[j] = pix / (H_IMG * W_IMG);
        const int rem = pix % (H_IMG * W_IMG);
        hh[j] = rem / W_IMG;
        ww[j] = rem % W_IMG;
    }

    wmma::fragment<wmma::accumulator, 16, 16, 16, float> acc[2][4];
    #pragma unroll
    for (int mt = 0; mt < 2; mt++)
        #pragma unroll
        for (int nt = 0; nt < 4; nt++)
            wmma::fill_fragment(acc[mt][nt], 0.0f);

    #pragma unroll 1
    for (int c = 0; c < 36; c++) {
        const int tap = c >> 2;             // 0..8 = kh*3+kw
        const int ch  = (c & 3) * 64;       // channel base of this k-chunk
        const int kh  = tap / 3 - 1;        // -1..1
        const int kw  = tap % 3 - 1;

        __syncthreads();   // previous chunk's compute done before overwrite

        // ---- stage A: 64 pixels x 64 channels ----
        #pragma unroll
        for (int j = 0; j < 2; j++) {
            const int hi = hh[j] + kh, wi = ww[j] + kw;
            const int row = r0 + j * 32;
            uint4* dst = reinterpret_cast<uint4*>(sm + row * APITCH + c8);
            if ((unsigned)hi < (unsigned)H_IMG && (unsigned)wi < (unsigned)W_IMG) {
                const int* src = x + (((int64_t)nn[j] * H_IMG + hi) * W_IMG + wi) * C_IN
                               + ch + c8;
                const int4 v0 = *reinterpret_cast<const int4*>(src);
                const int4 v1 = *reinterpret_cast<const int4*>(src + 4);
                __nv_bfloat162 p0 = __floats2bfloat162_rn((float)v0.x, (float)v0.y);
                __nv_bfloat162 p1 = __floats2bfloat162_rn((float)v0.z, (float)v0.w);
                __nv_bfloat162 p2 = __floats2bfloat162_rn((float)v1.x, (float)v1.y);
                __nv_bfloat162 p3 = __floats2bfloat162_rn((float)v1.z, (float)v1.w);
                uint4 pk;
                pk.x = *reinterpret_cast<uint32_t*>(&p0);
                pk.y = *reinterpret_cast<uint32_t*>(&p1);
                pk.z = *reinterpret_cast<uint32_t*>(&p2);
                pk.w = *reinterpret_cast<uint32_t*>(&p3);
                *dst = pk;
            } else {
                *dst = make_uint4(0u, 0u, 0u, 0u);
            }
        }

        // ---- stage B: 256 couts x 64 channels (same for all CTAs -> L2 hits) ----
        #pragma unroll
        for (int it = 0; it < 8; it++) {
            const int row = r0 + it * 32;   // cout
            const int* src = w + ((int64_t)row * 9 + tap) * C_IN + ch + c8;
            const int4 v0 = *reinterpret_cast<const int4*>(src);
            const int4 v1 = *reinterpret_cast<const int4*>(src + 4);
            __nv_bfloat162 p0 = __floats2bfloat162_rn((float)v0.x, (float)v0.y);
            __nv_bfloat162 p1 = __floats2bfloat162_rn((float)v0.z, (float)v0.w);
            __nv_bfloat162 p2 = __floats2bfloat162_rn((float)v1.x, (float)v1.y);
            __nv_bfloat162 p3 = __floats2bfloat162_rn((float)v1.z, (float)v1.w);
            uint4 pk;
            pk.x = *reinterpret_cast<uint32_t*>(&p0);
            pk.y = *reinterpret_cast<uint32_t*>(&p1);
            pk.z = *reinterpret_cast<uint32_t*>(&p2);
            pk.w = *reinterpret_cast<uint32_t*>(&p3);
            *reinterpret_cast<uint4*>(sm + B_OFF + row * BPITCH + c8) = pk;
        }

        __syncthreads();

        // ---- compute: 4 k-slices of 16 ----
        #pragma unroll
        for (int ks = 0; ks < 4; ks++) {
            wmma::fragment<wmma::matrix_a, 16, 16, 16, __nv_bfloat16,
                           wmma::row_major> af[2];
            #pragma unroll
            for (int mt = 0; mt < 2; mt++)
                wmma::load_matrix_sync(
                    af[mt], sm + (wm * 32 + mt * 16) * APITCH + ks * 16, APITCH);
            #pragma unroll
            for (int nt = 0; nt < 4; nt++) {
                wmma::fragment<wmma::matrix_b, 16, 16, 16, __nv_bfloat16,
                               wmma::col_major> bf;
                wmma::load_matrix_sync(
                    bf, sm + B_OFF + (wn * 64 + nt * 16) * BPITCH + ks * 16, BPITCH);
                #pragma unroll
                for (int mt = 0; mt < 2; mt++)
                    wmma::mma_sync(acc[mt][nt], af[mt], bf, acc[mt][nt]);
            }
        }
    }

    // ---- epilogue: store float32 VALUES (integer-exact in fp32) ----
    #pragma unroll
    for (int mt = 0; mt < 2; mt++)
        #pragma unroll
        for (int nt = 0; nt < 4; nt++) {
            float* dst = out
                       + (int64_t)(m_base + wm * 32 + mt * 16) * C_OUT
                       + wn * 64 + nt * 16;
            wmma::store_matrix_sync(dst, acc[mt][nt], C_OUT, wmma::mem_row_major);
        }
}

// ============================ host launch ============================
extern "C" void kernel_launch(void* const* d_in, const int* in_sizes, int n_in,
                              void* d_out, int out_size) {
    (void)out_size;
    // Bind inputs BY SIZE: x has 16*112*112*256 = 51,380,224 elements,
    // weight has 256*3*3*256 = 589,824. Robust to metadata ordering.
    const int* x = (const int*)d_in[0];
    const int* w = (const int*)d_in[1];
    if (n_in >= 2 && in_sizes[0] < in_sizes[1]) {
        x = (const int*)d_in[1];
        w = (const int*)d_in[0];
    }
    float* out = (float*)d_out;

    const int grid = (N_IMG * H_IMG * W_IMG) / 64;  // 3136
    conv_kernel<<<grid, 256>>>(x, w, out);
}